// round 15
// baseline (speedup 1.0000x reference)
#include <cuda_runtime.h>
#include <cuda_fp16.h>
#include <math.h>
#include <stdint.h>

// ---------------- problem constants ----------------
#define BATCH 16
#define CIN   256
#define NTOK  4096
#define MR    1024
#define HEADS 8

// ---------------- device scratch ----------------
__device__ __half g_r[(size_t)BATCH * MR * NTOK];    // exp(logits), UNNORMALIZED (fp16)
__device__ float  g_colsum[BATCH * NTOK];            // per-token sum of exp
__device__ float  g_zinv[BATCH * NTOK];              // 1/colsum
__device__ float  g_s[BATCH * MR];                   // region column sums (normalized probs)
__device__ float  g_xp[(size_t)BATCH * HEADS * CIN * 128];
__device__ float  g_pool[(size_t)BATCH * HEADS * 3 * 32 * 64];
__device__ float  g_vals[(size_t)BATCH * HEADS * 32 * 64];
__device__ float  g_W2[(size_t)BATCH * 256 * 512];

#define SWZ(bo) ((bo) ^ (((bo) >> 3) & 0x70))

// smem: two 128x64 fp16 tiles (128B rows, SW128-swizzled), 16KB each
#define SM_A 0
#define SM_B 16384
#define SMEM_ONE 32768

// ---------------- fp16 mma.sync (sm_80+) ----------------
__device__ __forceinline__ void mma16816(float* c, const uint32_t* a, uint32_t b0, uint32_t b1) {
    asm volatile(
        "mma.sync.aligned.m16n8k16.row.col.f32.f16.f16.f32 "
        "{%0,%1,%2,%3}, {%4,%5,%6,%7}, {%8,%9}, {%0,%1,%2,%3};"
        : "+f"(c[0]), "+f"(c[1]), "+f"(c[2]), "+f"(c[3])
        : "r"(a[0]), "r"(a[1]), "r"(a[2]), "r"(a[3]), "r"(b0), "r"(b1));
}

// ---- tile loaders -> fp16, SW128-swizzled [128 rows x 64 k] ----
// A slot, fp32 row-major source
__device__ __forceinline__ void load_A_f32(char* smem, const float* src, size_t rstride) {
    const int tid = threadIdx.x;
    #pragma unroll
    for (int it = 0; it < 16; it++) {
        const int i = tid + it * 256;
        const int row = i >> 5;
        const int kp = (i & 31) * 2;
        float2 v = *(const float2*)(src + (size_t)row * rstride + kp);
        __half2 h; h.x = __float2half(v.x); h.y = __float2half(v.y);
        *(__half2*)(smem + SM_A + SWZ((uint32_t)(row * 128 + kp * 2))) = h;
    }
}

// B slot, fp16 source scaled by per-token zinv; optional row-sum accumulation
// (fp32, pre-rounding). Thread i covers row = (tid>>3)+it*32, tokens (i&7)*8..+7.
__device__ __forceinline__ void copy_B_scaled(char* smem, const __half* src, size_t rstride,
                                              const float* zinv, float racc[4], int do_sum) {
    const int tid = threadIdx.x;
    #pragma unroll
    for (int it = 0; it < 4; it++) {
        const int i = tid + it * 256;
        const int row = i >> 3, ch = i & 7;
        __half2 v[4];
        *(uint4*)v = *(const uint4*)(src + (size_t)row * rstride + ch * 8);
        float4 z0 = *(const float4*)(zinv + ch * 8);
        float4 z1 = *(const float4*)(zinv + ch * 8 + 4);
        float f0 = __half2float(v[0].x) * z0.x, f1 = __half2float(v[0].y) * z0.y;
        float f2 = __half2float(v[1].x) * z0.z, f3 = __half2float(v[1].y) * z0.w;
        float f4 = __half2float(v[2].x) * z1.x, f5 = __half2float(v[2].y) * z1.y;
        float f6 = __half2float(v[3].x) * z1.z, f7 = __half2float(v[3].y) * z1.w;
        if (do_sum) racc[it] += ((f0 + f1) + (f2 + f3)) + ((f4 + f5) + (f6 + f7));
        __half2 h[4];
        h[0].x = __float2half(f0); h[0].y = __float2half(f1);
        h[1].x = __float2half(f2); h[1].y = __float2half(f3);
        h[2].x = __float2half(f4); h[2].y = __float2half(f5);
        h[3].x = __float2half(f6); h[3].y = __float2half(f7);
        *(uint4*)(smem + SM_B + SWZ((uint32_t)(row * 128 + ch * 16))) = *(uint4*)h;
    }
}

// B slot transposed, fp32 source S[k][n] (n contiguous) -> smem [n-row][k]
__device__ __forceinline__ void load_B_trans_f32(char* smem, const float* src, size_t nstride) {
    const int tid = threadIdx.x;
    #pragma unroll
    for (int it = 0; it < 32; it++) {
        const int i = tid + it * 256;
        const int k = i >> 7;
        const int n = i & 127;
        const float v = src[(size_t)k * nstride + n];
        *(__half*)(smem + SM_B + SWZ((uint32_t)(n * 128 + k * 2))) = __float2half(v);
    }
}

// B slot transposed, fp16 source S[k][n] -> smem [n-row][k], scaled by zinv[n]
__device__ __forceinline__ void load_B_trans_scaled(char* smem, const __half* src, size_t nstride,
                                                    const float* zinv) {
    const int tid = threadIdx.x;
    #pragma unroll
    for (int it = 0; it < 16; it++) {
        const int p = tid + it * 256;
        const int k = p >> 6;
        const int np = (p & 63) * 2;
        __half2 v = *(const __half2*)(src + (size_t)k * nstride + np);
        float2 z = *(const float2*)(zinv + np);
        *(__half*)(smem + SM_B + SWZ((uint32_t)(np * 128 + k * 2))) =
            __float2half(__half2float(v.x) * z.x);
        *(__half*)(smem + SM_B + SWZ((uint32_t)((np + 1) * 128 + k * 2))) =
            __float2half(__half2float(v.y) * z.y);
    }
}

// ---- per-chunk compute: warp tile 32(m) x 64(n), K=64 ----
__device__ __forceinline__ void compute_chunk(const char* sm, float acc[2][8][4],
                                              int wm, int wn, int g, int tig) {
    #pragma unroll
    for (int ks = 0; ks < 4; ks++) {
        const int kk = ks * 16;
        const int c0 = (kk + tig * 2) * 2;
        const int c1 = (kk + 8 + tig * 2) * 2;
        uint32_t a[2][4];
        #pragma unroll
        for (int mt = 0; mt < 2; mt++) {
            const int r0 = (wm + mt * 16 + g) * 128;
            const int r1 = r0 + 8 * 128;
            a[mt][0] = *(const uint32_t*)(sm + SWZ(r0 + c0));
            a[mt][1] = *(const uint32_t*)(sm + SWZ(r1 + c0));
            a[mt][2] = *(const uint32_t*)(sm + SWZ(r0 + c1));
            a[mt][3] = *(const uint32_t*)(sm + SWZ(r1 + c1));
        }
        #pragma unroll
        for (int nt = 0; nt < 8; nt++) {
            const int nr = (wn + nt * 8 + g) * 128;
            const uint32_t b0 = *(const uint32_t*)(sm + SM_B + SWZ(nr + c0));
            const uint32_t b1 = *(const uint32_t*)(sm + SM_B + SWZ(nr + c1));
            mma16816(acc[0][nt], a[0], b0, b1);
            mma16816(acc[1][nt], a[1], b0, b1);
        }
    }
}

// =====================================================================
// K0: zero g_colsum (65536)
// =====================================================================
__global__ void zero_colsum()
{
    g_colsum[blockIdx.x * 1024 + threadIdx.x] = 0.f;
}

// =====================================================================
// K1: r GEMM + fused exp + column sums.
// g_r[b] = exp(Wr @ X[b] + br)  (fp16, NO max-subtract: |logits| ~ O(1))
// =====================================================================
__global__ void __launch_bounds__(256, 2) tc_r_gemm(
    const float* __restrict__ x,
    const float* __restrict__ Wr, const float* __restrict__ br)
{
    extern __shared__ char smem[];
    const int tid = threadIdx.x;
    const int b = blockIdx.z, m0 = blockIdx.y * 128, n0 = blockIdx.x * 128;
    const float* X = x + (size_t)b * CIN * NTOK;

    const int lane = tid & 31, wid = tid >> 5;
    const int wm = (wid >> 1) * 32, wn = (wid & 1) * 64;
    const int g = lane >> 2, tig = lane & 3;

    float acc[2][8][4];
    #pragma unroll
    for (int i = 0; i < 2; i++)
        #pragma unroll
        for (int j = 0; j < 8; j++)
            #pragma unroll
            for (int k = 0; k < 4; k++) acc[i][j][k] = 0.f;

    #pragma unroll
    for (int c = 0; c < 4; c++) {
        load_A_f32(smem, Wr + (size_t)m0 * CIN + c * 64, CIN);
        load_B_trans_f32(smem, X + (size_t)(c * 64) * NTOK + n0, NTOK);
        __syncthreads();
        compute_chunk(smem, acc, wm, wn, g, tig);
        __syncthreads();
    }

    // epilogue: exp, store fp16, accumulate column sums
    float cs0[8], cs1[8];
    #pragma unroll
    for (int nt = 0; nt < 8; nt++) { cs0[nt] = 0.f; cs1[nt] = 0.f; }

    #pragma unroll
    for (int mt = 0; mt < 2; mt++) {
        const int m_a = m0 + wm + mt * 16 + g;
        const int m_b = m_a + 8;
        const float ba = br[m_a], bb = br[m_b];
        __half* Ca = g_r + (size_t)b * MR * NTOK + (size_t)m_a * NTOK + n0 + wn;
        __half* Cb = g_r + (size_t)b * MR * NTOK + (size_t)m_b * NTOK + n0 + wn;
        #pragma unroll
        for (int nt = 0; nt < 8; nt++) {
            const int nn = nt * 8 + tig * 2;
            const float e0 = __expf(acc[mt][nt][0] + ba);
            const float e1 = __expf(acc[mt][nt][1] + ba);
            const float e2 = __expf(acc[mt][nt][2] + bb);
            const float e3 = __expf(acc[mt][nt][3] + bb);
            __half2 va; va.x = __float2half(e0); va.y = __float2half(e1);
            __half2 vb; vb.x = __float2half(e2); vb.y = __float2half(e3);
            *(__half2*)(Ca + nn) = va;
            *(__half2*)(Cb + nn) = vb;
            cs0[nt] += e0 + e2;
            cs1[nt] += e1 + e3;
        }
    }

    // reduce over g (lanes differing in bits 2..4) -> lanes g==0 hold warp totals
    #pragma unroll
    for (int nt = 0; nt < 8; nt++) {
        #pragma unroll
        for (int off = 4; off <= 16; off <<= 1) {
            cs0[nt] += __shfl_xor_sync(0xffffffffu, cs0[nt], off);
            cs1[nt] += __shfl_xor_sync(0xffffffffu, cs1[nt], off);
        }
    }
    __syncthreads();
    float* cs = (float*)smem;
    if (tid < 128) cs[tid] = 0.f;
    __syncthreads();
    if (g == 0) {
        #pragma unroll
        for (int nt = 0; nt < 8; nt++) {
            atomicAdd(&cs[wn + nt * 8 + tig * 2], cs0[nt]);
            atomicAdd(&cs[wn + nt * 8 + tig * 2 + 1], cs1[nt]);
        }
    }
    __syncthreads();
    if (tid < 128) atomicAdd(&g_colsum[b * NTOK + n0 + tid], cs[tid]);
}

// =====================================================================
// K1.5: reciprocal of column sums
// =====================================================================
__global__ void inv_colsum()
{
    const int i = blockIdx.x * 1024 + threadIdx.x;
    g_zinv[i] = 1.0f / g_colsum[i];
}

// =====================================================================
// K3: pooling: Xp[bh] = X[b](256x4096) @ Rn[bh]^T(4096x128)
// zinv folded into B loads; m-tile-0 CTA computes g_s from loader values.
// grid (128 bh, 2 m-tiles). 64 K-chunks.
// =====================================================================
__global__ void __launch_bounds__(256, 2) tc_pool(const float* __restrict__ x)
{
    extern __shared__ char smem[];
    const int bh = blockIdx.x, b = bh >> 3, h = bh & 7;
    const int m0 = blockIdx.y * 128;
    const float* Asrc = x + (size_t)b * CIN * NTOK + (size_t)m0 * NTOK;
    const __half* Bsrc = g_r + (size_t)b * MR * NTOK + (size_t)(h * 128) * NTOK;
    const float* zinv = g_zinv + b * NTOK;
    const int do_sum = (blockIdx.y == 0);

    const int tid = threadIdx.x;
    const int lane = tid & 31, wid = tid >> 5;
    const int wm = (wid >> 1) * 32, wn = (wid & 1) * 64;
    const int g = lane >> 2, tig = lane & 3;

    float acc[2][8][4];
    #pragma unroll
    for (int i = 0; i < 2; i++)
        #pragma unroll
        for (int j = 0; j < 8; j++)
            #pragma unroll
            for (int k = 0; k < 4; k++) acc[i][j][k] = 0.f;

    float racc[4] = {0.f, 0.f, 0.f, 0.f};   // row sums for rows tid>>3 + it*32

    for (int c = 0; c < 64; c++) {
        load_A_f32(smem, Asrc + c * 64, NTOK);
        copy_B_scaled(smem, Bsrc + c * 64, NTOK, zinv + c * 64, racc, do_sum);
        __syncthreads();
        compute_chunk(smem, acc, wm, wn, g, tig);
        __syncthreads();
    }

    // write g_s: reduce over the 8 ch-threads of each row (consecutive lanes)
    if (do_sum) {
        #pragma unroll
        for (int it = 0; it < 4; it++) {
            float v = racc[it];
            v += __shfl_down_sync(0xffffffffu, v, 4);
            v += __shfl_down_sync(0xffffffffu, v, 2);
            v += __shfl_down_sync(0xffffffffu, v, 1);
            if ((tid & 7) == 0) {
                const int row = (tid >> 3) + it * 32;
                g_s[b * MR + h * 128 + row] = v;
            }
        }
    }

    float* Xp = g_xp + (size_t)bh * CIN * 128;
    #pragma unroll
    for (int mt = 0; mt < 2; mt++) {
        const int r_a = m0 + wm + mt * 16 + g;
        const int r_b = r_a + 8;
        #pragma unroll
        for (int nt = 0; nt < 8; nt++) {
            const int nn = wn + nt * 8 + tig * 2;
            float2 va; va.x = acc[mt][nt][0]; va.y = acc[mt][nt][1];
            float2 vb; vb.x = acc[mt][nt][2]; vb.y = acc[mt][nt][3];
            *(float2*)(Xp + (size_t)r_a * 128 + nn) = va;
            *(float2*)(Xp + (size_t)r_b * 128 + nn) = vb;
        }
    }
}

// =====================================================================
// K3.5: qr/kr/vr from pooled X. grid (128 bh, 2 jsub), 256 threads
// =====================================================================
__global__ void __launch_bounds__(256) qkvr_kernel(
    const float* __restrict__ Wqkv, const float* __restrict__ bqkv)
{
    const int bh = blockIdx.x;
    const int b = bh >> 3, h = bh & 7;
    const int jsub = blockIdx.y;
    const int tid = threadIdx.x;
    const int jloc = tid & 31;
    const int j = jsub * 32 + jloc;
    const int g = tid >> 5;

    __shared__ float Ws[96][33];
    __shared__ float Xs[32][129];
    const float* Xp = g_xp + (size_t)bh * CIN * 128;

    float acc[12];
    #pragma unroll
    for (int i = 0; i < 12; i++) acc[i] = 0.f;

    for (int c0 = 0; c0 < CIN; c0 += 32) {
        for (int idx = tid; idx < 96 * 32; idx += 256)
            Ws[idx >> 5][idx & 31] = Wqkv[(size_t)(h * 96 + (idx >> 5)) * CIN + c0 + (idx & 31)];
        for (int idx = tid; idx < 32 * 128; idx += 256)
            Xs[idx >> 7][idx & 127] = Xp[(size_t)(c0 + (idx >> 7)) * 128 + (idx & 127)];
        __syncthreads();
        #pragma unroll 8
        for (int cc = 0; cc < 32; cc++) {
            const float xq = Xs[cc][j];
            const float xk = Xs[cc][j + 64];
            #pragma unroll
            for (int i = 0; i < 12; i++) {
                const int row = g * 12 + i;
                acc[i] += Ws[row][cc] * (row < 32 ? xq : xk);
            }
        }
        __syncthreads();
    }

    float* out = g_pool + (size_t)bh * 3 * 2048;
    #pragma unroll
    for (int i = 0; i < 12; i++) {
        const int row = g * 12 + i;
        const int mat = row >> 5, d = row & 31;
        const int jj = (mat == 0) ? j : j + 64;
        const float Sv = g_s[b * MR + h * 128 + jj];
        out[mat * 2048 + d * 64 + j] = acc[i] + bqkv[h * 96 + row] * Sv;
    }
}

// =====================================================================
// K4: tiny region attention per (b,h)
// =====================================================================
__global__ void __launch_bounds__(256) attn_kernel()
{
    const int bh = blockIdx.x;
    const float* pool = g_pool + (size_t)bh * 3 * 2048;
    __shared__ float qr[2048], kr[2048], vr[2048];
    __shared__ float L[64][65];
    const int tid = threadIdx.x;

    for (int i = tid; i < 2048; i += 256) {
        qr[i] = pool[i]; kr[i] = pool[2048 + i]; vr[i] = pool[4096 + i];
    }
    __syncthreads();

    const float scale = rsqrtf(32.0f);
    for (int i = tid; i < 4096; i += 256) {
        const int q = i >> 6, k = i & 63;
        float s = 0.f;
        #pragma unroll
        for (int d = 0; d < 32; d++) s += qr[d * 64 + q] * kr[d * 64 + k];
        L[q][k] = s * scale;
    }
    __syncthreads();
    if (tid < 64) {
        const int q = tid;
        float m = -1e30f;
        #pragma unroll
        for (int k = 0; k < 64; k++) m = fmaxf(m, L[q][k]);
        float s = 0.f;
        #pragma unroll
        for (int k = 0; k < 64; k++) { const float e = __expf(L[q][k] - m); L[q][k] = e; s += e; }
        const float inv = 1.f / s;
        #pragma unroll
        for (int k = 0; k < 64; k++) L[q][k] *= inv;
    }
    __syncthreads();
    float* out = g_vals + (size_t)bh * 2048;
    for (int i = tid; i < 2048; i += 256) {
        const int d = i >> 6, q = i & 63;
        float s = 0.f;
        #pragma unroll
        for (int k = 0; k < 64; k++) s += vr[d * 64 + k] * L[q][k];
        out[i] = s;
    }
}

// =====================================================================
// K5: fold Wout into region values
// =====================================================================
__global__ void __launch_bounds__(256) w2_kernel(const float* __restrict__ Wout)
{
    const int b = blockIdx.y;
    const int i = blockIdx.x * 256 + threadIdx.x;
    const int c = i >> 9, hq = i & 511;
    const int h = hq >> 6, q = hq & 63;
    const float* vals = g_vals + (size_t)(b * 8 + h) * 2048;
    float s = 0.f;
    #pragma unroll
    for (int d = 0; d < 32; d++)
        s += Wout[c * 256 + h * 32 + d] * vals[d * 64 + q];
    g_W2[((size_t)b * 256 + c) * 512 + hq] = s;
}

// =====================================================================
// K6: expand GEMM + residual epilogue (zinv folded into B loads)
// =====================================================================
__global__ void __launch_bounds__(256, 2) tc_out(
    float* __restrict__ out, const float* __restrict__ x,
    const float* __restrict__ bout, const float* __restrict__ alpha)
{
    extern __shared__ char smem[];
    const int tid = threadIdx.x;
    const int b = blockIdx.z, m0 = blockIdx.y * 128, n0 = blockIdx.x * 128;
    const float* A = g_W2 + (size_t)b * 256 * 512;
    const __half* Rbase = g_r + (size_t)b * MR * NTOK;
    const float* zinv = g_zinv + b * NTOK + n0;

    const int lane = tid & 31, wid = tid >> 5;
    const int wm = (wid >> 1) * 32, wn = (wid & 1) * 64;
    const int g = lane >> 2, tig = lane & 3;

    float acc[2][8][4];
    #pragma unroll
    for (int i = 0; i < 2; i++)
        #pragma unroll
        for (int j = 0; j < 8; j++)
            #pragma unroll
            for (int k = 0; k < 4; k++) acc[i][j][k] = 0.f;

    for (int k0 = 0; k0 < 512; k0 += 64) {
        load_A_f32(smem, A + (size_t)m0 * 512 + k0, 512);
        // chunk k0 covers r rows (k0>>6)*128 .. +63 (the Rq half of each head)
        load_B_trans_scaled(smem, Rbase + (size_t)((k0 >> 6) * 128) * NTOK + n0, NTOK, zinv);
        __syncthreads();
        compute_chunk(smem, acc, wm, wn, g, tig);
        __syncthreads();
    }

    const float av = *alpha;
    #pragma unroll
    for (int mt = 0; mt < 2; mt++) {
        const int c_a = m0 + wm + mt * 16 + g;
        const int c_b = c_a + 8;
        const float ba = bout[c_a], bb = bout[c_b];
        const size_t base_a = ((size_t)b * 256 + c_a) * NTOK + n0 + wn;
        const size_t base_b = ((size_t)b * 256 + c_b) * NTOK + n0 + wn;
        #pragma unroll
        for (int nt = 0; nt < 8; nt++) {
            const int nn = nt * 8 + tig * 2;
            float2 xa = *(const float2*)(x + base_a + nn);
            float2 xb = *(const float2*)(x + base_b + nn);
            float2 oa, ob;
            oa.x = xa.x + av * (acc[mt][nt][0] + ba);
            oa.y = xa.y + av * (acc[mt][nt][1] + ba);
            ob.x = xb.x + av * (acc[mt][nt][2] + bb);
            ob.y = xb.y + av * (acc[mt][nt][3] + bb);
            *(float2*)(out + base_a + nn) = oa;
            *(float2*)(out + base_b + nn) = ob;
        }
    }
}

// =====================================================================
extern "C" void kernel_launch(void* const* d_in, const int* in_sizes, int n_in,
                              void* d_out, int out_size)
{
    const float* x     = (const float*)d_in[0];
    const float* Wqkv  = (const float*)d_in[1];
    const float* bqkv  = (const float*)d_in[2];
    const float* Wr    = (const float*)d_in[3];
    const float* br    = (const float*)d_in[4];
    const float* Wout  = (const float*)d_in[5];
    const float* bout  = (const float*)d_in[6];
    const float* alpha = (const float*)d_in[7];
    float* out = (float*)d_out;

    zero_colsum<<<BATCH * NTOK / 1024, 1024>>>();

    dim3 g1(NTOK / 128, MR / 128, BATCH);
    tc_r_gemm<<<g1, 256, SMEM_ONE>>>(x, Wr, br);

    inv_colsum<<<BATCH * NTOK / 1024, 1024>>>();

    dim3 g3(BATCH * HEADS, 2);
    tc_pool<<<g3, 256, SMEM_ONE>>>(x);

    dim3 g35(BATCH * HEADS, 2);
    qkvr_kernel<<<g35, 256>>>(Wqkv, bqkv);

    attn_kernel<<<BATCH * HEADS, 256>>>();

    w2_kernel<<<dim3(512, BATCH), 256>>>(Wout);

    dim3 g6(NTOK / 128, 256 / 128, BATCH);
    tc_out<<<g6, 256, SMEM_ONE>>>(out, x, bout, alpha);
}